// round 1
// baseline (speedup 1.0000x reference)
#include <cuda_runtime.h>
#include <stdint.h>

// Problem constants (match reference)
#define BB      1024        // batch
#define PP      512         // patches
#define KK      128         // dim
#define NM      819         // int(B*0.8)
#define NMR     921         // NM + int(B*0.1)
#define MAXC    76          // int(0.15*4096/8)
#define NTOT    67108864    // B*P*K
#define I_OFF   67108864
#define MT_OFF  (67108864 + 1024*76)

// Device globals (no allocation allowed)
__device__ uint32_t g_ks0, g_ks1, g_kr0, g_kr1;
__device__ int g_mode;
__device__ unsigned char g_sel[BB * PP];

// ---------------------------------------------------------------------------
// threefry2x32, exactly as in jax/_src/prng.py (5 groups of 4 rounds)
// ---------------------------------------------------------------------------
__device__ __forceinline__ uint2 tf2x32(uint32_t k0, uint32_t k1,
                                        uint32_t x0, uint32_t x1) {
    uint32_t k2 = k0 ^ k1 ^ 0x1BD11BDAu;
    x0 += k0; x1 += k1;
#define TFR(r) { x0 += x1; x1 = (x1 << (r)) | (x1 >> (32 - (r))); x1 ^= x0; }
    TFR(13) TFR(15) TFR(26) TFR(6)
    x0 += k1; x1 += k2 + 1u;
    TFR(17) TFR(29) TFR(16) TFR(24)
    x0 += k2; x1 += k0 + 2u;
    TFR(13) TFR(15) TFR(26) TFR(6)
    x0 += k0; x1 += k1 + 3u;
    TFR(17) TFR(29) TFR(16) TFR(24)
    x0 += k1; x1 += k2 + 4u;
    TFR(13) TFR(15) TFR(26) TFR(6)
    x0 += k2; x1 += k0 + 5u;
#undef TFR
    return make_uint2(x0, x1);
}

// Partitionable-threefry 32-bit random bits for element index i (i < 2^32):
// counter = (0, i), output = out0 ^ out1.
__device__ __forceinline__ uint32_t rbits32(uint32_t k0, uint32_t k1, uint32_t i) {
    uint2 r = tf2x32(k0, k1, 0u, i);
    return r.x ^ r.y;
}

// ---------------------------------------------------------------------------
// Kernel 1: derive keys, compute permutation of 1024 (JAX _shuffle, 1 round),
// write mask_type, store mode = mask_type[0].
// ---------------------------------------------------------------------------
__global__ void k_perm(float* __restrict__ mt_out) {
    __shared__ unsigned long long sk[1024];
    __shared__ uint32_t sub0, sub1;
    int tid = threadIdx.x;
    if (tid == 0) {
        // root key for seed 42 is (0, 42)
        // fold-like split(key, 3): key_i = threefry(key, (0, i))
        uint2 kp = tf2x32(0u, 42u, 0u, 0u);
        uint2 ks = tf2x32(0u, 42u, 0u, 1u);
        uint2 kr = tf2x32(0u, 42u, 0u, 2u);
        g_ks0 = ks.x; g_ks1 = ks.y;
        g_kr0 = kr.x; g_kr1 = kr.y;
        // _shuffle: key, subkey = split(kp); subkey = threefry(kp, (0,1))
        uint2 sub = tf2x32(kp.x, kp.y, 0u, 1u);
        sub0 = sub.x; sub1 = sub.y;
    }
    __syncthreads();
    uint32_t bits = rbits32(sub0, sub1, (uint32_t)tid);
    // stable sort_key_val(bits, arange) -> composite 64-bit key
    sk[tid] = ((unsigned long long)bits << 10) | (unsigned)tid;
    for (int size = 2; size <= 1024; size <<= 1) {
        for (int stride = size >> 1; stride > 0; stride >>= 1) {
            __syncthreads();
            int j = tid ^ stride;
            if (j > tid) {
                unsigned long long a = sk[tid], b = sk[j];
                bool asc = ((tid & size) == 0);
                if ((a > b) == asc) { sk[tid] = b; sk[j] = a; }
            }
        }
    }
    __syncthreads();
    int perm = (int)(sk[tid] & 1023ull);
    int grp = (tid < NM) ? 0 : ((tid < NMR) ? 1 : 2);
    mt_out[perm] = (float)grp;
    if (perm == 0) g_mode = grp;
}

// ---------------------------------------------------------------------------
// Kernel 2: per-row scores + stable argsort; write sel map + padded I.
// One block per batch row, 512 threads.
// ---------------------------------------------------------------------------
__global__ void k_scores(const int* __restrict__ seq_len, float* __restrict__ I_out) {
    __shared__ unsigned long long sk[PP];
    int b = blockIdx.x;
    int p = threadIdx.x;
    int sl = seq_len[b];
    int nv = sl >> 3;  // seq_len // PATCH
    uint32_t i = (uint32_t)(b * PP + p);
    // uniform(ks,(B,P)) ordering == ordering of 23-bit mantissa (bits >> 9)
    uint32_t m = rbits32(g_ks0, g_ks1, i) >> 9;
    uint32_t keyhi = (p < nv) ? m : 0x00800000u;  // +inf sentinel > any mantissa
    sk[p] = ((unsigned long long)keyhi << 32) | (unsigned)p;  // index tiebreak = stable
    for (int size = 2; size <= PP; size <<= 1) {
        for (int stride = size >> 1; stride > 0; stride >>= 1) {
            __syncthreads();
            int j = p ^ stride;
            if (j > p) {
                unsigned long long a = sk[p], bv = sk[j];
                bool asc = ((p & size) == 0);
                if ((a > bv) == asc) { sk[p] = bv; sk[j] = a; }
            }
        }
    }
    __syncthreads();
    int ord = (int)(uint32_t)sk[p];  // order[p] : patch id at sorted rank p
    // n_corr = floor(0.15f * float(seq_len) / 8.0f), f32 rounding as in JAX
    int nc = (int)floorf(0.15f * (float)sl / 8.0f);
    // sel[order[j]] = (j < nc): each patch appears exactly once -> full coverage
    g_sel[b * PP + ord] = (p < nc) ? 1 : 0;
    if (p < MAXC) I_out[b * MAXC + p] = (p < nc) ? (float)ord : -1.0f;
}

// ---------------------------------------------------------------------------
// Kernel 3: main output pass, float4 vectorized. Threefry only for selected
// elements in mode 1.
// ---------------------------------------------------------------------------
__global__ void k_main(const float* __restrict__ x, const float* __restrict__ pos,
                       const float* __restrict__ wm, float* __restrict__ out) {
    int t = blockIdx.x * blockDim.x + threadIdx.x;  // 16,777,216 float4 slots
    int e = t << 2;                                  // element index < 2^27
    int mode = g_mode;
    bool s = g_sel[e >> 7] != 0;  // (b*512+p)
    float4 o;
    if (!s || mode == 2) {
        o = ((const float4*)x)[t];
    } else {
        float4 po = *(const float4*)(pos + (e & 65535));  // pos[p*K + k]
        if (mode == 0) {
            float4 w = *(const float4*)(wm + (e & 127));
            o = make_float4(w.x + po.x, w.y + po.y, w.z + po.z, w.w + po.w);
        } else {
            uint32_t kr0 = g_kr0, kr1 = g_kr1;
            float u[4];
#pragma unroll
            for (int j = 0; j < 4; j++) {
                uint32_t bits = rbits32(kr0, kr1, (uint32_t)(e + j));
                u[j] = __uint_as_float((bits >> 9) | 0x3f800000u) - 1.0f;
            }
            o = make_float4(u[0] + po.x, u[1] + po.y, u[2] + po.z, u[3] + po.w);
        }
    }
    ((float4*)out)[t] = o;
}

// ---------------------------------------------------------------------------
extern "C" void kernel_launch(void* const* d_in, const int* in_sizes, int n_in,
                              void* d_out, int out_size) {
    const float* x   = (const float*)d_in[0];
    const float* pos = (const float*)d_in[1];
    const float* wm  = (const float*)d_in[2];
    const int* sl    = (const int*)d_in[3];
    float* out = (float*)d_out;

    k_perm<<<1, 1024>>>(out + MT_OFF);
    k_scores<<<BB, PP>>>(sl, out + I_OFF);
    k_main<<<NTOT / 4 / 256, 256>>>(x, pos, wm, out);
}